// round 16
// baseline (speedup 1.0000x reference)
#include <cuda_runtime.h>
#include <cuda_fp16.h>
#include <math.h>
#include <stdint.h>

#define NBM 64
#define TT 1024
#define CC 768
#define NH 12
#define DD 64
#define EPSV 1e-6f
#define RTOT 65536

// ---- scratch (device globals; allocation-free contract) ----
__device__ __align__(1024) __half g_xh[RTOT * CC];
__device__ __align__(1024) __half g_wh[2][CC * CC];   // [0]=wk, [1]=wq
__device__ float g_kk  [NBM * NH * TT];
__device__ float g_kpart[NBM * NH * 8 * DD];
__device__ float g_ksum[NBM * NH * DD];
__device__ float g_upart[2][NBM * NH * CC];
__device__ float g_z   [NBM * NH * TT];
__device__ float g_ws  [NBM * NH * CC];

// ---------------- PTX helpers (base-target sm_80+) ----------------
__device__ __forceinline__ uint32_t smem_u32(const void* p) {
    uint32_t a;
    asm("{ .reg .u64 t; cvta.to.shared.u64 t, %1; cvt.u32.u64 %0, t; }" : "=r"(a) : "l"(p));
    return a;
}
__device__ __forceinline__ void cp16(uint32_t dst, const void* src) {
    asm volatile("cp.async.cg.shared.global [%0], [%1], 16;" :: "r"(dst), "l"(src));
}
__device__ __forceinline__ void cp_commit() {
    asm volatile("cp.async.commit_group;" ::: "memory");
}
__device__ __forceinline__ void cp_wait3() { asm volatile("cp.async.wait_group 3;" ::: "memory"); }
__device__ __forceinline__ void ldm4(uint32_t* r, uint32_t addr) {
    asm volatile("ldmatrix.sync.aligned.m8n8.x4.shared.b16 {%0,%1,%2,%3}, [%4];"
        : "=r"(r[0]), "=r"(r[1]), "=r"(r[2]), "=r"(r[3]) : "r"(addr));
}
__device__ __forceinline__ void mma16816(float* c, const uint32_t* a, const uint32_t* b) {
    asm volatile(
        "mma.sync.aligned.m16n8k16.row.col.f32.f16.f16.f32 "
        "{%0,%1,%2,%3}, {%4,%5,%6,%7}, {%8,%9}, {%0,%1,%2,%3};"
        : "+f"(c[0]), "+f"(c[1]), "+f"(c[2]), "+f"(c[3])
        : "r"(a[0]), "r"(a[1]), "r"(a[2]), "r"(a[3]), "r"(b[0]), "r"(b[1]));
}

// ---------------- fp32 -> fp16 (x, wk, wq in one launch) ----------------
__global__ __launch_bounds__(256) void conv_all(
    const float4* __restrict__ x, const float4* __restrict__ wk,
    const float4* __restrict__ wq,
    __half2* __restrict__ xh, __half2* __restrict__ wkh,
    __half2* __restrict__ wqh, int n4x, int n4w)
{
    int i = blockIdx.x * blockDim.x + threadIdx.x;
    const float4* in;
    __half2* out;
    int j;
    if (i < n4x) { in = x; out = xh; j = i; }
    else if (i < n4x + n4w) { in = wk; out = wkh; j = i - n4x; }
    else if (i < n4x + 2 * n4w) { in = wq; out = wqh; j = i - n4x - n4w; }
    else return;
    float4 v = in[j];
    out[2 * j]     = __floats2half2_rn(v.x, v.y);
    out[2 * j + 1] = __floats2half2_rn(v.z, v.w);
}

// ---------------- warp-MMA projection GEMM (single-pass fp16) ----------------
// CTA: 128 rows x 128 cols (2 heads), 256 threads, 8 warps (2x4) of 64x32
// warp tiles, K-step 32, 5-stage cp.async ring, 2 CTAs/SM.
// Iteration order: wait -> sync -> compute(kk=0) -> issue loads -> compute(kk=1).
// mode 0 (K): epilogue -> g_kk, g_kpart.  mode 1 (Q): epilogue -> g_z.
#define BK 32
#define STRIDE_B 80                   // 32 halfs (64B) + 16B pad
#define A_OFF 0
#define B_OFF 10240
#define STAGE_BYTES 20480
#define NSTAGE 5
#define KSTEPS 24
#define PROJ_SMEM (NSTAGE * STAGE_BYTES)

__device__ __forceinline__ void load_stage(
    uint32_t st, const __half* a, const __half* b,
    int r0, int c0, int k0, int tid)
{
    #pragma unroll
    for (int q = 0; q < 2; q++) {          // A: 128 rows x 4 chunks
        int u = q * 256 + tid;
        int row = u >> 2, ch = u & 3;
        cp16(st + A_OFF + row * STRIDE_B + ch * 16,
             a + (size_t)(r0 + row) * CC + k0 + ch * 8);
    }
    #pragma unroll
    for (int q = 0; q < 2; q++) {          // B: 128 rows x 4 chunks
        int u = q * 256 + tid;
        int row = u >> 2, ch = u & 3;
        cp16(st + B_OFF + row * STRIDE_B + ch * 16,
             b + (size_t)(c0 + row) * CC + k0 + ch * 8);
    }
}

__global__ __launch_bounds__(256, 2) void proj_mma(
    const __half* __restrict__ a, const __half* __restrict__ bw,
    const float* __restrict__ bias, int mode)
{
    extern __shared__ char sm[];
    __shared__ float sbias[128];
    __shared__ float sks[128];
    __shared__ float rowred[4][128];
    __shared__ float colred[2][4][32];

    const int tid = threadIdx.x;
    const int wid = tid >> 5, lane = tid & 31;
    const int warp_m = wid >> 2;          // 0..1 (64 rows)
    const int warp_n = wid & 3;           // 0..3 (32 cols)
    const int ct = blockIdx.x;            // 0..5 (2 heads each)
    const int ry = blockIdx.y;            // 0..511
    const int r0 = ry << 7, c0 = ct << 7;
    const int bm = ry >> 3, tl = ry & 7;
    const uint32_t sb = smem_u32(sm);

    if (tid < 128) {
        sbias[tid] = bias[c0 + tid];
        if (mode == 1)
            sks[tid] = g_ksum[((size_t)bm * NH + ct * 2 + (tid >> 6)) * DD + (tid & 63)];
    }

    float acc[4][4][4];
    #pragma unroll
    for (int mi = 0; mi < 4; mi++)
        #pragma unroll
        for (int ni = 0; ni < 4; ni++)
            #pragma unroll
            for (int r = 0; r < 4; r++) acc[mi][ni][r] = 0.f;

    const uint32_t aoff = (uint32_t)((lane & 15) * STRIDE_B + (lane >> 4) * 16);
    const uint32_t boff = (uint32_t)(((lane & 7) + ((lane >> 4) & 1) * 8) * STRIDE_B
                                     + ((lane >> 3) & 1) * 16);

    // prologue: stages 0..3 in flight (4 groups)
    #pragma unroll
    for (int s = 0; s < NSTAGE - 1; s++) {
        load_stage(sb + (uint32_t)(s * STAGE_BYTES), a, bw, r0, c0, s * BK, tid);
        cp_commit();
    }

    for (int ks = 0; ks < KSTEPS; ks++) {
        cp_wait3();        // groups <= 3 outstanding -> stage ks retired
        __syncthreads();   // all warps finished reading stage ks-1

        const uint32_t st = sb + (uint32_t)((ks % NSTAGE) * STAGE_BYTES);

        // ---- kk = 0: compute first so HMMA issues right after barrier ----
        {
            uint32_t af[4][4], bf[2][4];
            #pragma unroll
            for (int mi = 0; mi < 4; mi++)
                ldm4(af[mi], st + A_OFF + (uint32_t)((warp_m * 64 + mi * 16) * STRIDE_B) + aoff);
            #pragma unroll
            for (int ng = 0; ng < 2; ng++)
                ldm4(bf[ng], st + B_OFF + (uint32_t)((warp_n * 32 + ng * 16) * STRIDE_B) + boff);
            #pragma unroll
            for (int mi = 0; mi < 4; mi++)
                #pragma unroll
                for (int ng = 0; ng < 2; ng++) {
                    mma16816(acc[mi][2 * ng],     af[mi], &bf[ng][0]);
                    mma16816(acc[mi][2 * ng + 1], af[mi], &bf[ng][2]);
                }
        }

        // ---- prefetch stage ks+4 ----
        if (ks + NSTAGE - 1 < KSTEPS)
            load_stage(sb + (uint32_t)(((ks + NSTAGE - 1) % NSTAGE) * STAGE_BYTES),
                       a, bw, r0, c0, (ks + NSTAGE - 1) * BK, tid);
        cp_commit();       // real or empty: exactly one group per iteration

        // ---- kk = 1 ----
        {
            uint32_t af[4][4], bf[2][4];
            #pragma unroll
            for (int mi = 0; mi < 4; mi++)
                ldm4(af[mi], st + A_OFF + (uint32_t)((warp_m * 64 + mi * 16) * STRIDE_B) + 32 + aoff);
            #pragma unroll
            for (int ng = 0; ng < 2; ng++)
                ldm4(bf[ng], st + B_OFF + (uint32_t)((warp_n * 32 + ng * 16) * STRIDE_B) + 32 + boff);
            #pragma unroll
            for (int mi = 0; mi < 4; mi++)
                #pragma unroll
                for (int ng = 0; ng < 2; ng++) {
                    mma16816(acc[mi][2 * ng],     af[mi], &bf[ng][0]);
                    mma16816(acc[mi][2 * ng + 1], af[mi], &bf[ng][2]);
                }
        }
    }

    // ---------------- fused epilogue ----------------
    const int cb = warp_n * 32 + 2 * (lane & 3);
    float colacc[4][2];
    #pragma unroll
    for (int ni = 0; ni < 4; ni++) { colacc[ni][0] = 0.f; colacc[ni][1] = 0.f; }

    #pragma unroll
    for (int mi = 0; mi < 4; mi++) {
        float rs0 = 0.f, rs1 = 0.f;
        #pragma unroll
        for (int ni = 0; ni < 4; ni++) {
            const float b0 = sbias[cb + ni * 8], b1 = sbias[cb + ni * 8 + 1];
            #pragma unroll
            for (int r = 0; r < 4; r++) {
                float pre = acc[mi][ni][r] + ((r & 1) ? b1 : b0);
                float v = (pre > 0.f) ? (pre + 1.f) : __expf(pre);
                if (mode == 0) {
                    colacc[ni][r & 1] += v;
                    if (r < 2) rs0 += v; else rs1 += v;
                } else {
                    float w = sks[cb + ni * 8 + (r & 1)];
                    if (r < 2) rs0 += v * w; else rs1 += v * w;
                }
            }
        }
        rs0 += __shfl_xor_sync(0xffffffffu, rs0, 1);
        rs0 += __shfl_xor_sync(0xffffffffu, rs0, 2);
        rs1 += __shfl_xor_sync(0xffffffffu, rs1, 1);
        rs1 += __shfl_xor_sync(0xffffffffu, rs1, 2);
        if ((lane & 3) == 0) {
            int row = warp_m * 64 + mi * 16 + (lane >> 2);
            rowred[warp_n][row]     = rs0;
            rowred[warp_n][row + 8] = rs1;
        }
    }

    if (mode == 0) {
        #pragma unroll
        for (int ni = 0; ni < 4; ni++)
            #pragma unroll
            for (int j = 0; j < 2; j++) {
                float c = colacc[ni][j];
                c += __shfl_xor_sync(0xffffffffu, c, 4);
                c += __shfl_xor_sync(0xffffffffu, c, 8);
                c += __shfl_xor_sync(0xffffffffu, c, 16);
                if (lane < 4)
                    colred[warp_m][warp_n][ni * 8 + lane * 2 + j] = c;
            }
    }
    __syncthreads();

    if (mode == 0) {
        {
            int hh = tid >> 7, row = tid & 127;   // hh 0..1
            float v = rowred[2 * hh][row] + rowred[2 * hh + 1][row];
            g_kk[((size_t)bm * NH + ct * 2 + hh) * TT + tl * 128 + row] = v;
        }
        if (tid < 128) {
            int wn = tid >> 5, c = tid & 31;
            int col = wn * 32 + c;
            int hh = col >> 6, d = col & 63;
            float v = colred[0][wn][c] + colred[1][wn][c];
            g_kpart[(((size_t)bm * NH + ct * 2 + hh) * 8 + tl) * DD + d] = v;
        }
    } else {
        int hh = tid >> 7, row = tid & 127;
        float sum = rowred[2 * hh][row] + rowred[2 * hh + 1][row];
        g_z[((size_t)bm * NH + ct * 2 + hh) * TT + tl * 128 + row] = 1.f / (sum + EPSV);
    }
}

// ---------------- ksum reduce ----------------
__global__ void reduce_ksum_kernel()
{
    int idx = blockIdx.x * blockDim.x + threadIdx.x;
    if (idx < NBM * NH * DD) {
        int hh = idx >> 6, d = idx & 63;
        float s = 0.f;
        #pragma unroll
        for (int p = 0; p < 8; p++)
            s += g_kpart[((size_t)hh * 8 + p) * DD + d];
        g_ksum[idx] = s;
    }
}

// ---- u partials: g_upart[z][bm,n,c] = sum_{t in half z} kk[bm,n,t]*xh[bm,t,c]
// t-loop unrolled x8 with a batched load phase -> MLP ~8 (was ~2).
__global__ __launch_bounds__(128) void u_kernel()
{
    __shared__ float skk[NH][512];
    const int bm = blockIdx.y, c0 = blockIdx.x * 256, tid = threadIdx.x;
    const int t0 = blockIdx.z * 512;
    for (int idx = tid; idx < NH * 512; idx += 128)
        skk[idx >> 9][idx & 511] =
            g_kk[((size_t)bm * NH + (idx >> 9)) * TT + t0 + (idx & 511)];
    __syncthreads();
    float acc[NH][2];
    #pragma unroll
    for (int nn = 0; nn < NH; nn++) { acc[nn][0] = 0.f; acc[nn][1] = 0.f; }
    const __half* xp = g_xh + ((size_t)bm * TT + t0) * CC + c0 + 2 * tid;
    for (int t = 0; t < 512; t += 8) {
        float2 xv[8];
        #pragma unroll
        for (int q = 0; q < 8; q++)
            xv[q] = __half22float2(*(const __half2*)(xp + (size_t)(t + q) * CC));
        #pragma unroll
        for (int q = 0; q < 8; q++) {
            #pragma unroll
            for (int nn = 0; nn < NH; nn++) {
                float kv = skk[nn][t + q];
                acc[nn][0] = fmaf(kv, xv[q].x, acc[nn][0]);
                acc[nn][1] = fmaf(kv, xv[q].y, acc[nn][1]);
            }
        }
    }
    #pragma unroll
    for (int nn = 0; nn < NH; nn++) {
        float* up = g_upart[blockIdx.z] + ((size_t)bm * NH + nn) * CC + c0 + 2 * tid;
        up[0] = acc[nn][0];
        up[1] = acc[nn][1];
    }
}

// ---- fused s+ws: per (n, bm-group of 16):
//   s[bm, n*64+c] = u[bm,n,:].wv[n*64+c,:] + bv*Kt  (kept in smem)
//   ws[bm,n,j]    = sum_e s[bm,n*64+e] * wp[j, n*64+e]
__global__ __launch_bounds__(256) void sws_kernel(
    const float* __restrict__ wv, const float* __restrict__ bv,
    const float* __restrict__ wp)
{
    __shared__ __align__(16) float swv[64][65];   // [k][c]  (reused as wp tile)
    __shared__ __align__(16) float su[64][17];    // [k][bm]
    __shared__ __align__(16) float ssl[16][65];   // [bm][c] s-slice
    __shared__ float sKt[16];
    const int n = blockIdx.x, bmg = blockIdx.y * 16, tid = threadIdx.x;
    if (tid < 16) {
        float s = 0.f;
        #pragma unroll
        for (int d = 0; d < DD; d++)
            s += g_ksum[((size_t)(bmg + tid) * NH + n) * DD + d];
        sKt[tid] = s;
    }
    const int c = tid & 63, bq = tid >> 6;
    float acc[4] = {0.f, 0.f, 0.f, 0.f};

    for (int kc = 0; kc < 12; kc++) {
        __syncthreads();
        {
            int row = tid >> 2, k16 = (tid & 3) * 16;
            const float* wr = wv + (size_t)(n * 64 + row) * CC + kc * 64 + k16;
            #pragma unroll
            for (int i = 0; i < 4; i++) {
                float4 v = *(const float4*)(wr + i * 4);
                swv[k16 + i * 4 + 0][row] = v.x; swv[k16 + i * 4 + 1][row] = v.y;
                swv[k16 + i * 4 + 2][row] = v.z; swv[k16 + i * 4 + 3][row] = v.w;
            }
        }
        {
            int row = tid >> 4, k4 = (tid & 15) * 4;
            size_t off = ((size_t)(bmg + row) * NH + n) * CC + kc * 64 + k4;
            float4 v0 = *(const float4*)(g_upart[0] + off);
            float4 v1 = *(const float4*)(g_upart[1] + off);
            su[k4 + 0][row] = v0.x + v1.x; su[k4 + 1][row] = v0.y + v1.y;
            su[k4 + 2][row] = v0.z + v1.z; su[k4 + 3][row] = v0.w + v1.w;
        }
        __syncthreads();
        #pragma unroll 8
        for (int k = 0; k < 64; k++) {
            float w = swv[k][c];
            #pragma unroll
            for (int i = 0; i < 4; i++)
                acc[i] = fmaf(su[k][bq * 4 + i], w, acc[i]);
        }
    }
    #pragma unroll
    for (int i = 0; i < 4; i++)
        ssl[bq * 4 + i][c] = acc[i] + bv[n * 64 + c] * sKt[bq * 4 + i];
    __syncthreads();

    // ---- phase 2: ws over 12 j-tiles of 64 ----
    const int jl = tid & 63;    // j within tile
    for (int jt = 0; jt < 12; jt++) {
        {
            int row = tid >> 2, e16 = (tid & 3) * 16;
            const float* wr = wp + (size_t)(jt * 64 + row) * CC + n * 64 + e16;
            #pragma unroll
            for (int i = 0; i < 4; i++) {
                float4 v = *(const float4*)(wr + i * 4);
                swv[e16 + i * 4 + 0][row] = v.x; swv[e16 + i * 4 + 1][row] = v.y;
                swv[e16 + i * 4 + 2][row] = v.z; swv[e16 + i * 4 + 3][row] = v.w;
            }
        }
        __syncthreads();
        float wsum[4] = {0.f, 0.f, 0.f, 0.f};
        #pragma unroll 8
        for (int e = 0; e < 64; e++) {
            float w = swv[e][jl];
            #pragma unroll
            for (int i = 0; i < 4; i++)
                wsum[i] = fmaf(ssl[bq * 4 + i][e], w, wsum[i]);
        }
        #pragma unroll
        for (int i = 0; i < 4; i++) {
            int bmv = bmg + bq * 4 + i;
            g_ws[((size_t)bmv * NH + n) * CC + jt * 64 + jl] = wsum[i];
        }
        __syncthreads();
    }
}

// ---- out[bm,t,j] = sum_n z[n,t]*ws[n,j] + bp[j] ----
__global__ __launch_bounds__(256) void out_kernel(
    const float* __restrict__ bp, float* __restrict__ out)
{
    __shared__ __align__(16) float sws[NH][CC];
    __shared__ __align__(16) float sbp[CC];
    __shared__ float sz[NH][128];
    const int bm = blockIdx.y, t0 = blockIdx.x * 128, tid = threadIdx.x;
    for (int idx = tid; idx < NH * CC; idx += 256)
        sws[idx / CC][idx % CC] = g_ws[(size_t)bm * NH * CC + idx];
    for (int idx = tid; idx < CC; idx += 256) sbp[idx] = bp[idx];
    for (int idx = tid; idx < NH * 128; idx += 256)
        sz[idx >> 7][idx & 127] =
            g_z[((size_t)bm * NH + (idx >> 7)) * TT + t0 + (idx & 127)];
    __syncthreads();

    const int r = tid >> 1, half = tid & 1;
    float z[NH];
    #pragma unroll
    for (int n = 0; n < NH; n++) z[n] = sz[n][r];
    float4* out4 = (float4*)(out + ((size_t)bm * TT + t0 + r) * CC);
    const float4* bp4 = (const float4*)sbp;
    for (int k = 0; k < 96; k++) {
        int c4 = half * 96 + k;
        float4 acc = bp4[c4];
        #pragma unroll
        for (int n = 0; n < NH; n++) {
            float4 w = *(const float4*)&sws[n][c4 * 4];
            acc.x = fmaf(z[n], w.x, acc.x);
            acc.y = fmaf(z[n], w.y, acc.y);
            acc.z = fmaf(z[n], w.z, acc.z);
            acc.w = fmaf(z[n], w.w, acc.w);
        }
        out4[c4] = acc;
    }
}

// ---------------- host ----------------
extern "C" void kernel_launch(void* const* d_in, const int* in_sizes, int n_in,
                              void* d_out, int out_size)
{
    const float* x  = (const float*)d_in[0];
    const float* wq = (const float*)d_in[1];
    const float* bq = (const float*)d_in[2];
    const float* wk = (const float*)d_in[3];
    const float* bk = (const float*)d_in[4];
    const float* wv = (const float*)d_in[5];
    const float* bv = (const float*)d_in[6];
    const float* wp = (const float*)d_in[7];
    const float* bp = (const float*)d_in[8];
    float* out = (float*)d_out;

    cudaFuncSetAttribute(proj_mma, cudaFuncAttributeMaxDynamicSharedMemorySize, PROJ_SMEM);

    __half *xh, *wkh, *wqh;
    cudaGetSymbolAddress((void**)&xh, g_xh);
    cudaGetSymbolAddress((void**)&wkh, g_wh);
    wqh = wkh + CC * CC;

    const int n4x = RTOT * CC / 4;
    const int n4w = CC * CC / 4;
    conv_all<<<(n4x + 2 * n4w + 255) / 256, 256>>>(
        (const float4*)x, (const float4*)wk, (const float4*)wq,
        (__half2*)xh, (__half2*)wkh, (__half2*)wqh, n4x, n4w);

    dim3 pg(6, 512);
    proj_mma<<<pg, 256, PROJ_SMEM>>>(xh, wkh, bk, 0);   // K -> kk, kpart
    reduce_ksum_kernel<<<(NBM * NH * DD + 255) / 256, 256>>>();
    u_kernel<<<dim3(3, NBM, 2), 128>>>();
    sws_kernel<<<dim3(NH, 4), 256>>>(wv, bv, wp);
    proj_mma<<<pg, 256, PROJ_SMEM>>>(xh, wqh, bq, 1);   // Q -> z
    out_kernel<<<dim3(8, NBM), 256>>>(bp, out);
}

// round 17
// speedup vs baseline: 1.0637x; 1.0637x over previous
#include <cuda_runtime.h>
#include <cuda_fp16.h>
#include <math.h>
#include <stdint.h>

#define NBM 64
#define TT 1024
#define CC 768
#define NH 12
#define DD 64
#define EPSV 1e-6f
#define RTOT 65536

// ---- scratch (device globals; allocation-free contract) ----
__device__ __align__(1024) __half g_xh[RTOT * CC];
__device__ __align__(1024) __half g_wh[2][CC * CC];   // [0]=wk, [1]=wq
__device__ float g_kk  [NBM * NH * TT];
__device__ float g_kpart[NBM * NH * 8 * DD];
__device__ float g_ksum[NBM * NH * DD];
__device__ float g_upart[4][NBM * NH * CC];
__device__ float g_z   [NBM * NH * TT];
__device__ float g_ws  [NBM * NH * CC];

// ---------------- PTX helpers (base-target sm_80+) ----------------
__device__ __forceinline__ uint32_t smem_u32(const void* p) {
    uint32_t a;
    asm("{ .reg .u64 t; cvta.to.shared.u64 t, %1; cvt.u32.u64 %0, t; }" : "=r"(a) : "l"(p));
    return a;
}
__device__ __forceinline__ void cp16(uint32_t dst, const void* src) {
    asm volatile("cp.async.cg.shared.global [%0], [%1], 16;" :: "r"(dst), "l"(src));
}
__device__ __forceinline__ void cp_commit() {
    asm volatile("cp.async.commit_group;" ::: "memory");
}
__device__ __forceinline__ void cp_wait3() { asm volatile("cp.async.wait_group 3;" ::: "memory"); }
__device__ __forceinline__ void ldm4(uint32_t* r, uint32_t addr) {
    asm volatile("ldmatrix.sync.aligned.m8n8.x4.shared.b16 {%0,%1,%2,%3}, [%4];"
        : "=r"(r[0]), "=r"(r[1]), "=r"(r[2]), "=r"(r[3]) : "r"(addr));
}
__device__ __forceinline__ void mma16816(float* c, const uint32_t* a, const uint32_t* b) {
    asm volatile(
        "mma.sync.aligned.m16n8k16.row.col.f32.f16.f16.f32 "
        "{%0,%1,%2,%3}, {%4,%5,%6,%7}, {%8,%9}, {%0,%1,%2,%3};"
        : "+f"(c[0]), "+f"(c[1]), "+f"(c[2]), "+f"(c[3])
        : "r"(a[0]), "r"(a[1]), "r"(a[2]), "r"(a[3]), "r"(b[0]), "r"(b[1]));
}

// ---------------- fp32 -> fp16 (x, wk, wq in one launch) ----------------
__global__ __launch_bounds__(256) void conv_all(
    const float4* __restrict__ x, const float4* __restrict__ wk,
    const float4* __restrict__ wq,
    __half2* __restrict__ xh, __half2* __restrict__ wkh,
    __half2* __restrict__ wqh, int n4x, int n4w)
{
    int i = blockIdx.x * blockDim.x + threadIdx.x;
    const float4* in;
    __half2* out;
    int j;
    if (i < n4x) { in = x; out = xh; j = i; }
    else if (i < n4x + n4w) { in = wk; out = wkh; j = i - n4x; }
    else if (i < n4x + 2 * n4w) { in = wq; out = wqh; j = i - n4x - n4w; }
    else return;
    float4 v = in[j];
    out[2 * j]     = __floats2half2_rn(v.x, v.y);
    out[2 * j + 1] = __floats2half2_rn(v.z, v.w);
}

// ---------------- warp-MMA projection GEMM (single-pass fp16) ----------------
// CTA: 128 rows x 128 cols (2 heads), 256 threads, 8 warps (2x4) of 64x32
// warp tiles, K-step 32, 5-stage cp.async ring, 2 CTAs/SM.
// Iteration order: wait -> sync -> compute(kk=0) -> issue loads -> compute(kk=1).
// mode 0 (K): epilogue -> g_kk, g_kpart.  mode 1 (Q): epilogue -> g_z.
#define BK 32
#define STRIDE_B 80                   // 32 halfs (64B) + 16B pad
#define A_OFF 0
#define B_OFF 10240
#define STAGE_BYTES 20480
#define NSTAGE 5
#define KSTEPS 24
#define PROJ_SMEM (NSTAGE * STAGE_BYTES)

__device__ __forceinline__ void load_stage(
    uint32_t st, const __half* a, const __half* b,
    int r0, int c0, int k0, int tid)
{
    #pragma unroll
    for (int q = 0; q < 2; q++) {          // A: 128 rows x 4 chunks
        int u = q * 256 + tid;
        int row = u >> 2, ch = u & 3;
        cp16(st + A_OFF + row * STRIDE_B + ch * 16,
             a + (size_t)(r0 + row) * CC + k0 + ch * 8);
    }
    #pragma unroll
    for (int q = 0; q < 2; q++) {          // B: 128 rows x 4 chunks
        int u = q * 256 + tid;
        int row = u >> 2, ch = u & 3;
        cp16(st + B_OFF + row * STRIDE_B + ch * 16,
             b + (size_t)(c0 + row) * CC + k0 + ch * 8);
    }
}

__global__ __launch_bounds__(256, 2) void proj_mma(
    const __half* __restrict__ a, const __half* __restrict__ bw,
    const float* __restrict__ bias, int mode)
{
    extern __shared__ char sm[];
    __shared__ float sbias[128];
    __shared__ float sks[128];
    __shared__ float rowred[4][128];
    __shared__ float colred[2][4][32];

    const int tid = threadIdx.x;
    const int wid = tid >> 5, lane = tid & 31;
    const int warp_m = wid >> 2;          // 0..1 (64 rows)
    const int warp_n = wid & 3;           // 0..3 (32 cols)
    const int ct = blockIdx.x;            // 0..5 (2 heads each)
    const int ry = blockIdx.y;            // 0..511
    const int r0 = ry << 7, c0 = ct << 7;
    const int bm = ry >> 3, tl = ry & 7;
    const uint32_t sb = smem_u32(sm);

    if (tid < 128) {
        sbias[tid] = bias[c0 + tid];
        if (mode == 1)
            sks[tid] = g_ksum[((size_t)bm * NH + ct * 2 + (tid >> 6)) * DD + (tid & 63)];
    }

    float acc[4][4][4];
    #pragma unroll
    for (int mi = 0; mi < 4; mi++)
        #pragma unroll
        for (int ni = 0; ni < 4; ni++)
            #pragma unroll
            for (int r = 0; r < 4; r++) acc[mi][ni][r] = 0.f;

    const uint32_t aoff = (uint32_t)((lane & 15) * STRIDE_B + (lane >> 4) * 16);
    const uint32_t boff = (uint32_t)(((lane & 7) + ((lane >> 4) & 1) * 8) * STRIDE_B
                                     + ((lane >> 3) & 1) * 16);

    // prologue: stages 0..3 in flight (4 groups)
    #pragma unroll
    for (int s = 0; s < NSTAGE - 1; s++) {
        load_stage(sb + (uint32_t)(s * STAGE_BYTES), a, bw, r0, c0, s * BK, tid);
        cp_commit();
    }

    for (int ks = 0; ks < KSTEPS; ks++) {
        cp_wait3();        // groups <= 3 outstanding -> stage ks retired
        __syncthreads();   // all warps finished reading stage ks-1

        const uint32_t st = sb + (uint32_t)((ks % NSTAGE) * STAGE_BYTES);

        // ---- kk = 0: compute first so HMMA issues right after barrier ----
        {
            uint32_t af[4][4], bf[2][4];
            #pragma unroll
            for (int mi = 0; mi < 4; mi++)
                ldm4(af[mi], st + A_OFF + (uint32_t)((warp_m * 64 + mi * 16) * STRIDE_B) + aoff);
            #pragma unroll
            for (int ng = 0; ng < 2; ng++)
                ldm4(bf[ng], st + B_OFF + (uint32_t)((warp_n * 32 + ng * 16) * STRIDE_B) + boff);
            #pragma unroll
            for (int mi = 0; mi < 4; mi++)
                #pragma unroll
                for (int ng = 0; ng < 2; ng++) {
                    mma16816(acc[mi][2 * ng],     af[mi], &bf[ng][0]);
                    mma16816(acc[mi][2 * ng + 1], af[mi], &bf[ng][2]);
                }
        }

        // ---- prefetch stage ks+4 ----
        if (ks + NSTAGE - 1 < KSTEPS)
            load_stage(sb + (uint32_t)(((ks + NSTAGE - 1) % NSTAGE) * STAGE_BYTES),
                       a, bw, r0, c0, (ks + NSTAGE - 1) * BK, tid);
        cp_commit();       // real or empty: exactly one group per iteration

        // ---- kk = 1 ----
        {
            uint32_t af[4][4], bf[2][4];
            #pragma unroll
            for (int mi = 0; mi < 4; mi++)
                ldm4(af[mi], st + A_OFF + (uint32_t)((warp_m * 64 + mi * 16) * STRIDE_B) + 32 + aoff);
            #pragma unroll
            for (int ng = 0; ng < 2; ng++)
                ldm4(bf[ng], st + B_OFF + (uint32_t)((warp_n * 32 + ng * 16) * STRIDE_B) + 32 + boff);
            #pragma unroll
            for (int mi = 0; mi < 4; mi++)
                #pragma unroll
                for (int ng = 0; ng < 2; ng++) {
                    mma16816(acc[mi][2 * ng],     af[mi], &bf[ng][0]);
                    mma16816(acc[mi][2 * ng + 1], af[mi], &bf[ng][2]);
                }
        }
    }

    // ---------------- fused epilogue ----------------
    const int cb = warp_n * 32 + 2 * (lane & 3);
    float colacc[4][2];
    #pragma unroll
    for (int ni = 0; ni < 4; ni++) { colacc[ni][0] = 0.f; colacc[ni][1] = 0.f; }

    #pragma unroll
    for (int mi = 0; mi < 4; mi++) {
        float rs0 = 0.f, rs1 = 0.f;
        #pragma unroll
        for (int ni = 0; ni < 4; ni++) {
            const float b0 = sbias[cb + ni * 8], b1 = sbias[cb + ni * 8 + 1];
            #pragma unroll
            for (int r = 0; r < 4; r++) {
                float pre = acc[mi][ni][r] + ((r & 1) ? b1 : b0);
                float v = (pre > 0.f) ? (pre + 1.f) : __expf(pre);
                if (mode == 0) {
                    colacc[ni][r & 1] += v;
                    if (r < 2) rs0 += v; else rs1 += v;
                } else {
                    float w = sks[cb + ni * 8 + (r & 1)];
                    if (r < 2) rs0 += v * w; else rs1 += v * w;
                }
            }
        }
        rs0 += __shfl_xor_sync(0xffffffffu, rs0, 1);
        rs0 += __shfl_xor_sync(0xffffffffu, rs0, 2);
        rs1 += __shfl_xor_sync(0xffffffffu, rs1, 1);
        rs1 += __shfl_xor_sync(0xffffffffu, rs1, 2);
        if ((lane & 3) == 0) {
            int row = warp_m * 64 + mi * 16 + (lane >> 2);
            rowred[warp_n][row]     = rs0;
            rowred[warp_n][row + 8] = rs1;
        }
    }

    if (mode == 0) {
        #pragma unroll
        for (int ni = 0; ni < 4; ni++)
            #pragma unroll
            for (int j = 0; j < 2; j++) {
                float c = colacc[ni][j];
                c += __shfl_xor_sync(0xffffffffu, c, 4);
                c += __shfl_xor_sync(0xffffffffu, c, 8);
                c += __shfl_xor_sync(0xffffffffu, c, 16);
                if (lane < 4)
                    colred[warp_m][warp_n][ni * 8 + lane * 2 + j] = c;
            }
    }
    __syncthreads();

    if (mode == 0) {
        {
            int hh = tid >> 7, row = tid & 127;   // hh 0..1
            float v = rowred[2 * hh][row] + rowred[2 * hh + 1][row];
            g_kk[((size_t)bm * NH + ct * 2 + hh) * TT + tl * 128 + row] = v;
        }
        if (tid < 128) {
            int wn = tid >> 5, c = tid & 31;
            int col = wn * 32 + c;
            int hh = col >> 6, d = col & 63;
            float v = colred[0][wn][c] + colred[1][wn][c];
            g_kpart[(((size_t)bm * NH + ct * 2 + hh) * 8 + tl) * DD + d] = v;
        }
    } else {
        int hh = tid >> 7, row = tid & 127;
        float sum = rowred[2 * hh][row] + rowred[2 * hh + 1][row];
        g_z[((size_t)bm * NH + ct * 2 + hh) * TT + tl * 128 + row] = 1.f / (sum + EPSV);
    }
}

// ---------------- ksum reduce ----------------
__global__ void reduce_ksum_kernel()
{
    int idx = blockIdx.x * blockDim.x + threadIdx.x;
    if (idx < NBM * NH * DD) {
        int hh = idx >> 6, d = idx & 63;
        float s = 0.f;
        #pragma unroll
        for (int p = 0; p < 8; p++)
            s += g_kpart[((size_t)hh * 8 + p) * DD + d];
        g_ksum[idx] = s;
    }
}

// ---- u partials: g_upart[z][bm,n,c] = sum_{t in quarter z} kk[bm,n,t]*xh[bm,t,c]
// grid (3, NBM, 4): 768 blocks -> ~2x warps in flight vs the 2-way split.
__global__ __launch_bounds__(128) void u_kernel()
{
    __shared__ float skk[NH][256];
    const int bm = blockIdx.y, c0 = blockIdx.x * 256, tid = threadIdx.x;
    const int t0 = blockIdx.z * 256;
    for (int idx = tid; idx < NH * 256; idx += 128)
        skk[idx >> 8][idx & 255] =
            g_kk[((size_t)bm * NH + (idx >> 8)) * TT + t0 + (idx & 255)];
    __syncthreads();
    float acc[NH][2];
    #pragma unroll
    for (int nn = 0; nn < NH; nn++) { acc[nn][0] = 0.f; acc[nn][1] = 0.f; }
    const __half* xp = g_xh + ((size_t)bm * TT + t0) * CC + c0 + 2 * tid;
    for (int t = 0; t < 256; t++) {
        float2 xv = __half22float2(*(const __half2*)(xp + (size_t)t * CC));
        #pragma unroll
        for (int nn = 0; nn < NH; nn++) {
            float kv = skk[nn][t];
            acc[nn][0] = fmaf(kv, xv.x, acc[nn][0]);
            acc[nn][1] = fmaf(kv, xv.y, acc[nn][1]);
        }
    }
    #pragma unroll
    for (int nn = 0; nn < NH; nn++) {
        float* up = g_upart[blockIdx.z] + ((size_t)bm * NH + nn) * CC + c0 + 2 * tid;
        up[0] = acc[nn][0];
        up[1] = acc[nn][1];
    }
}

// ---- fused s+ws: per (n, bm-group of 16):
//   s[bm, n*64+c] = u[bm,n,:].wv[n*64+c,:] + bv*Kt  (kept in smem)
//   ws[bm,n,j]    = sum_e s[bm,n*64+e] * wp[j, n*64+e]
__global__ __launch_bounds__(256) void sws_kernel(
    const float* __restrict__ wv, const float* __restrict__ bv,
    const float* __restrict__ wp)
{
    __shared__ __align__(16) float swv[64][65];   // [k][c]  (reused as wp tile)
    __shared__ __align__(16) float su[64][17];    // [k][bm]
    __shared__ __align__(16) float ssl[16][65];   // [bm][c] s-slice
    __shared__ float sKt[16];
    const int n = blockIdx.x, bmg = blockIdx.y * 16, tid = threadIdx.x;
    if (tid < 16) {
        float s = 0.f;
        #pragma unroll
        for (int d = 0; d < DD; d++)
            s += g_ksum[((size_t)(bmg + tid) * NH + n) * DD + d];
        sKt[tid] = s;
    }
    const int c = tid & 63, bq = tid >> 6;
    float acc[4] = {0.f, 0.f, 0.f, 0.f};

    for (int kc = 0; kc < 12; kc++) {
        __syncthreads();
        {
            int row = tid >> 2, k16 = (tid & 3) * 16;
            const float* wr = wv + (size_t)(n * 64 + row) * CC + kc * 64 + k16;
            #pragma unroll
            for (int i = 0; i < 4; i++) {
                float4 v = *(const float4*)(wr + i * 4);
                swv[k16 + i * 4 + 0][row] = v.x; swv[k16 + i * 4 + 1][row] = v.y;
                swv[k16 + i * 4 + 2][row] = v.z; swv[k16 + i * 4 + 3][row] = v.w;
            }
        }
        {
            int row = tid >> 4, k4 = (tid & 15) * 4;
            size_t off = ((size_t)(bmg + row) * NH + n) * CC + kc * 64 + k4;
            float4 v0 = *(const float4*)(g_upart[0] + off);
            float4 v1 = *(const float4*)(g_upart[1] + off);
            float4 v2 = *(const float4*)(g_upart[2] + off);
            float4 v3 = *(const float4*)(g_upart[3] + off);
            su[k4 + 0][row] = ((v0.x + v1.x) + v2.x) + v3.x;
            su[k4 + 1][row] = ((v0.y + v1.y) + v2.y) + v3.y;
            su[k4 + 2][row] = ((v0.z + v1.z) + v2.z) + v3.z;
            su[k4 + 3][row] = ((v0.w + v1.w) + v2.w) + v3.w;
        }
        __syncthreads();
        #pragma unroll 8
        for (int k = 0; k < 64; k++) {
            float w = swv[k][c];
            #pragma unroll
            for (int i = 0; i < 4; i++)
                acc[i] = fmaf(su[k][bq * 4 + i], w, acc[i]);
        }
    }
    #pragma unroll
    for (int i = 0; i < 4; i++)
        ssl[bq * 4 + i][c] = acc[i] + bv[n * 64 + c] * sKt[bq * 4 + i];
    __syncthreads();

    // ---- phase 2: ws over 12 j-tiles of 64 ----
    const int jl = tid & 63;    // j within tile
    for (int jt = 0; jt < 12; jt++) {
        {
            int row = tid >> 2, e16 = (tid & 3) * 16;
            const float* wr = wp + (size_t)(jt * 64 + row) * CC + n * 64 + e16;
            #pragma unroll
            for (int i = 0; i < 4; i++) {
                float4 v = *(const float4*)(wr + i * 4);
                swv[e16 + i * 4 + 0][row] = v.x; swv[e16 + i * 4 + 1][row] = v.y;
                swv[e16 + i * 4 + 2][row] = v.z; swv[e16 + i * 4 + 3][row] = v.w;
            }
        }
        __syncthreads();
        float wsum[4] = {0.f, 0.f, 0.f, 0.f};
        #pragma unroll 8
        for (int e = 0; e < 64; e++) {
            float w = swv[e][jl];
            #pragma unroll
            for (int i = 0; i < 4; i++)
                wsum[i] = fmaf(ssl[bq * 4 + i][e], w, wsum[i]);
        }
        #pragma unroll
        for (int i = 0; i < 4; i++) {
            int bmv = bmg + bq * 4 + i;
            g_ws[((size_t)bmv * NH + n) * CC + jt * 64 + jl] = wsum[i];
        }
        __syncthreads();
    }
}

// ---- out[bm,t,j] = sum_n z[n,t]*ws[n,j] + bp[j] ----
__global__ __launch_bounds__(256) void out_kernel(
    const float* __restrict__ bp, float* __restrict__ out)
{
    __shared__ __align__(16) float sws[NH][CC];
    __shared__ __align__(16) float sbp[CC];
    __shared__ float sz[NH][128];
    const int bm = blockIdx.y, t0 = blockIdx.x * 128, tid = threadIdx.x;
    for (int idx = tid; idx < NH * CC; idx += 256)
        sws[idx / CC][idx % CC] = g_ws[(size_t)bm * NH * CC + idx];
    for (int idx = tid; idx < CC; idx += 256) sbp[idx] = bp[idx];
    for (int idx = tid; idx < NH * 128; idx += 256)
        sz[idx >> 7][idx & 127] =
            g_z[((size_t)bm * NH + (idx >> 7)) * TT + t0 + (idx & 127)];
    __syncthreads();

    const int r = tid >> 1, half = tid & 1;
    float z[NH];
    #pragma unroll
    for (int n = 0; n < NH; n++) z[n] = sz[n][r];
    float4* out4 = (float4*)(out + ((size_t)bm * TT + t0 + r) * CC);
    const float4* bp4 = (const float4*)sbp;
    for (int k = 0; k < 96; k++) {
        int c4 = half * 96 + k;
        float4 acc = bp4[c4];
        #pragma unroll
        for (int n = 0; n < NH; n++) {
            float4 w = *(const float4*)&sws[n][c4 * 4];
            acc.x = fmaf(z[n], w.x, acc.x);
            acc.y = fmaf(z[n], w.y, acc.y);
            acc.z = fmaf(z[n], w.z, acc.z);
            acc.w = fmaf(z[n], w.w, acc.w);
        }
        out4[c4] = acc;
    }
}

// ---------------- host ----------------
extern "C" void kernel_launch(void* const* d_in, const int* in_sizes, int n_in,
                              void* d_out, int out_size)
{
    const float* x  = (const float*)d_in[0];
    const float* wq = (const float*)d_in[1];
    const float* bq = (const float*)d_in[2];
    const float* wk = (const float*)d_in[3];
    const float* bk = (const float*)d_in[4];
    const float* wv = (const float*)d_in[5];
    const float* bv = (const float*)d_in[6];
    const float* wp = (const float*)d_in[7];
    const float* bp = (const float*)d_in[8];
    float* out = (float*)d_out;

    cudaFuncSetAttribute(proj_mma, cudaFuncAttributeMaxDynamicSharedMemorySize, PROJ_SMEM);

    __half *xh, *wkh, *wqh;
    cudaGetSymbolAddress((void**)&xh, g_xh);
    cudaGetSymbolAddress((void**)&wkh, g_wh);
    wqh = wkh + CC * CC;

    const int n4x = RTOT * CC / 4;
    const int n4w = CC * CC / 4;
    conv_all<<<(n4x + 2 * n4w + 255) / 256, 256>>>(
        (const float4*)x, (const float4*)wk, (const float4*)wq,
        (__half2*)xh, (__half2*)wkh, (__half2*)wqh, n4x, n4w);

    dim3 pg(6, 512);
    proj_mma<<<pg, 256, PROJ_SMEM>>>(xh, wkh, bk, 0);   // K -> kk, kpart
    reduce_ksum_kernel<<<(NBM * NH * DD + 255) / 256, 256>>>();
    u_kernel<<<dim3(3, NBM, 4), 128>>>();
    sws_kernel<<<dim3(NH, 4), 256>>>(wv, bv, wp);
    proj_mma<<<pg, 256, PROJ_SMEM>>>(xh, wqh, bq, 1);   // Q -> z
    out_kernel<<<dim3(8, NBM), 256>>>(bp, out);
}